// round 1
// baseline (speedup 1.0000x reference)
#include <cuda_runtime.h>
#include <cuda_bf16.h>
#include <math.h>

#define N_ATOMS 20000
#define N_EDGES 320000
#define FEAT 128
#define N_RBF 20
#define N_CONV 3
#define CUTOFF 5.0f
#define PI_F 3.14159265358979323846f

// ---------------- scratch (allowed: __device__ globals) ----------------
__device__ float g_s   [N_ATOMS * 128];
__device__ float g_vA  [N_ATOMS * 384];
__device__ float g_vB  [N_ATOMS * 384];
__device__ float g_phi [N_ATOMS * 384];   // reused as "split"
__device__ float g_uv  [N_ATOMS * 384];
__device__ float g_vv  [N_ATOMS * 384];
__device__ float g_cat [N_ATOMS * 256];
__device__ float g_t1  [N_ATOMS * 128];
__device__ float g_t2  [N_ATOMS * 128];
__device__ float g_af  [N_ATOMS * 64];
__device__ int   g_cnt [N_ATOMS];
__device__ int   g_cur [N_ATOMS];
__device__ int   g_rowptr[N_ATOMS + 1];
__device__ int   g_ej  [N_EDGES];
__device__ float4 g_eu4[N_EDGES];          // unit.x,y,z, f_cut
__device__ float g_erbf[N_EDGES * N_RBF];  // rbf * f_cut

__device__ __forceinline__ float silu_f(float x) {
    return x / (1.0f + __expf(-x));
}

// ---------------- small utility kernels ----------------
__global__ void zero_f_kernel(float* p, int n) {
    for (int i = blockIdx.x * blockDim.x + threadIdx.x; i < n; i += gridDim.x * blockDim.x)
        p[i] = 0.0f;
}
__global__ void zero_i_kernel(int* p, int n) {
    int i = blockIdx.x * blockDim.x + threadIdx.x;
    if (i < n) p[i] = 0;
}

__global__ void init_s_kernel(float* __restrict__ s, const float* __restrict__ embed,
                              const int* __restrict__ z) {
    int gid = blockIdx.x * blockDim.x + threadIdx.x;
    if (gid >= N_ATOMS * 128) return;
    int n = gid >> 7;
    int f = gid & 127;
    s[gid] = embed[z[n] * 128 + f];
}

__global__ void count_kernel(int* __restrict__ cnt, const int* __restrict__ nbrs) {
    int e = blockIdx.x * blockDim.x + threadIdx.x;
    if (e >= N_EDGES) return;
    atomicAdd(&cnt[nbrs[2 * e]], 1);
}

__global__ void scan_kernel(const int* __restrict__ cnt, int* __restrict__ rowptr,
                            int* __restrict__ cur) {
    __shared__ int part[1024];
    const int t = threadIdx.x;
    const int CH = (N_ATOMS + 1023) / 1024;  // 20
    int base = t * CH;
    int sum = 0;
    for (int i = 0; i < CH; i++) {
        int a = base + i;
        if (a < N_ATOMS) sum += cnt[a];
    }
    part[t] = sum;
    __syncthreads();
    for (int d = 1; d < 1024; d <<= 1) {
        int add = (t >= d) ? part[t - d] : 0;
        __syncthreads();
        part[t] += add;
        __syncthreads();
    }
    int run = part[t] - sum;  // exclusive prefix
    for (int i = 0; i < CH; i++) {
        int a = base + i;
        if (a < N_ATOMS) {
            rowptr[a] = run;
            cur[a] = run;
            run += cnt[a];
        }
    }
    if (t == 1023) rowptr[N_ATOMS] = part[1023];
}

__global__ void fill_kernel(const int* __restrict__ nbrs, const float* __restrict__ xyz,
                            int* __restrict__ cur, int* __restrict__ ej,
                            float4* __restrict__ eu4, float* __restrict__ erbf) {
    int e = blockIdx.x * blockDim.x + threadIdx.x;
    if (e >= N_EDGES) return;
    int i = nbrs[2 * e];
    int j = nbrs[2 * e + 1];
    float rx = xyz[3 * j + 0] - xyz[3 * i + 0];
    float ry = xyz[3 * j + 1] - xyz[3 * i + 1];
    float rz = xyz[3 * j + 2] - xyz[3 * i + 2];
    float d2 = rx * rx + ry * ry + rz * rz + 1e-12f;
    float d = sqrtf(d2);
    float inv = 1.0f / d;
    float fc = (d < CUTOFF) ? 0.5f * (cosf(PI_F * d / CUTOFF) + 1.0f) : 0.0f;
    int pos = atomicAdd(&cur[i], 1);
    ej[pos] = j;
    eu4[pos] = make_float4(rx * inv, ry * inv, rz * inv, fc);
    float invfc = inv * fc;
    float arg = PI_F * d / CUTOFF;
#pragma unroll
    for (int k = 0; k < N_RBF; k++) {
        erbf[(size_t)pos * N_RBF + k] = sinf((float)(k + 1) * arg) * invfc;
    }
}

// ---------------- tiled SGEMM with optional silu epilogue ----------------
// C[M,N] = act(A[M,K] @ B[K,N] + bias).  N must be a multiple of BN, K a multiple of BK.
template <int BM, int BN, int BK, int CM, int CN, bool ACT>
__global__ void sgemm_kernel(const float* __restrict__ A, const float* __restrict__ B,
                             const float* __restrict__ bias, float* __restrict__ C,
                             int M, int N, int K) {
    constexpr int TX = BN / (4 * CN);
    constexpr int TY = BM / (4 * CM);
    constexpr int NT = TX * TY;
    __shared__ float As[BK][BM + 4];
    __shared__ float Bs[BK][BN];
    const int tid = threadIdx.x;
    const int tx = tid % TX;
    const int ty = tid / TX;
    const int m0 = blockIdx.y * BM;
    const int n0 = blockIdx.x * BN;

    float acc[CM][CN][4][4];
#pragma unroll
    for (int a = 0; a < CM; a++)
#pragma unroll
        for (int b = 0; b < CN; b++)
#pragma unroll
            for (int i = 0; i < 4; i++)
#pragma unroll
                for (int jj = 0; jj < 4; jj++) acc[a][b][i][jj] = 0.0f;

    for (int k0 = 0; k0 < K; k0 += BK) {
#pragma unroll 4
        for (int idx = tid; idx < BM * BK; idx += NT) {
            int m = idx / BK;
            int kk = idx % BK;
            int gm = m0 + m;
            As[kk][m] = (gm < M) ? A[(size_t)gm * K + k0 + kk] : 0.0f;
        }
#pragma unroll 4
        for (int idx = tid; idx < BK * BN; idx += NT) {
            int kk = idx / BN;
            int n = idx % BN;
            Bs[kk][n] = B[(size_t)(k0 + kk) * N + n0 + n];
        }
        __syncthreads();
#pragma unroll
        for (int kk = 0; kk < BK; kk++) {
            float av[CM][4], bv[CN][4];
#pragma unroll
            for (int cm = 0; cm < CM; cm++) {
                float4 v = *(const float4*)&As[kk][cm * TY * 4 + ty * 4];
                av[cm][0] = v.x; av[cm][1] = v.y; av[cm][2] = v.z; av[cm][3] = v.w;
            }
#pragma unroll
            for (int cn = 0; cn < CN; cn++) {
                float4 v = *(const float4*)&Bs[kk][cn * TX * 4 + tx * 4];
                bv[cn][0] = v.x; bv[cn][1] = v.y; bv[cn][2] = v.z; bv[cn][3] = v.w;
            }
#pragma unroll
            for (int cm = 0; cm < CM; cm++)
#pragma unroll
                for (int cn = 0; cn < CN; cn++)
#pragma unroll
                    for (int i = 0; i < 4; i++)
#pragma unroll
                        for (int jj = 0; jj < 4; jj++)
                            acc[cm][cn][i][jj] = fmaf(av[cm][i], bv[cn][jj], acc[cm][cn][i][jj]);
        }
        __syncthreads();
    }

#pragma unroll
    for (int cn = 0; cn < CN; cn++) {
        int col = n0 + cn * TX * 4 + tx * 4;
        float4 bb = make_float4(0.f, 0.f, 0.f, 0.f);
        if (bias) bb = *(const float4*)&bias[col];
#pragma unroll
        for (int cm = 0; cm < CM; cm++)
#pragma unroll
            for (int i = 0; i < 4; i++) {
                int row = m0 + cm * TY * 4 + ty * 4 + i;
                if (row < M) {
                    float4 r;
                    r.x = acc[cm][cn][i][0] + bb.x;
                    r.y = acc[cm][cn][i][1] + bb.y;
                    r.z = acc[cm][cn][i][2] + bb.z;
                    r.w = acc[cm][cn][i][3] + bb.w;
                    if (ACT) {
                        r.x = silu_f(r.x); r.y = silu_f(r.y);
                        r.z = silu_f(r.z); r.w = silu_f(r.w);
                    }
                    *(float4*)&C[(size_t)row * N + col] = r;
                }
            }
    }
}

// ---------------- edge aggregation (CSR gather, no atomics) ----------------
// For each atom i: s[i] += sum_e inv1 ; vnew[i] = vold[i] + sum_e (unit*inv2 + inv0*vold[j])
// where inv_c[f] = phi[j, c*128+f] * w_s[c*128+f],
//       w_s = (rbf*fc) @ Wd + bd*fc   (rbf*fc precomputed per edge)
__global__ void aggregate_kernel(const float* __restrict__ phi, const float* __restrict__ vold,
                                 float* __restrict__ vnew, float* __restrict__ s,
                                 const float* __restrict__ Wd, const float* __restrict__ bd,
                                 const int* __restrict__ rowptr, const int* __restrict__ ej,
                                 const float4* __restrict__ eu4, const float* __restrict__ erbf) {
    __shared__ float sWd[N_RBF * 384];
    __shared__ float sRbf[N_RBF];
    const int t = threadIdx.x;  // 128 threads = one feature each
    for (int idx = t; idx < N_RBF * 384; idx += 128) sWd[idx] = Wd[idx];
    const float bd0 = bd[t];
    const float bd1 = bd[128 + t];
    const float bd2 = bd[256 + t];
    __syncthreads();

    for (int atom = blockIdx.x; atom < N_ATOMS; atom += gridDim.x) {
        const int e0 = rowptr[atom];
        const int e1 = rowptr[atom + 1];
        float ds = 0.0f, dv0 = 0.0f, dv1 = 0.0f, dv2 = 0.0f;
        for (int e = e0; e < e1; e++) {
            const int j = ej[e];
            const float4 u = eu4[e];
            if (t < N_RBF) sRbf[t] = erbf[(size_t)e * N_RBF + t];
            __syncthreads();
            float ws0 = bd0 * u.w, ws1 = bd1 * u.w, ws2 = bd2 * u.w;
#pragma unroll
            for (int k = 0; k < N_RBF; k++) {
                float r = sRbf[k];
                ws0 = fmaf(r, sWd[k * 384 + t], ws0);
                ws1 = fmaf(r, sWd[k * 384 + 128 + t], ws1);
                ws2 = fmaf(r, sWd[k * 384 + 256 + t], ws2);
            }
            const float* pj = phi + (size_t)j * 384;
            const float inv0 = pj[t] * ws0;
            const float inv1 = pj[128 + t] * ws1;
            const float inv2 = pj[256 + t] * ws2;
            ds += inv1;
            const float* vj = vold + (size_t)j * 384;
            dv0 = fmaf(u.x, inv2, fmaf(inv0, vj[t], dv0));
            dv1 = fmaf(u.y, inv2, fmaf(inv0, vj[128 + t], dv1));
            dv2 = fmaf(u.z, inv2, fmaf(inv0, vj[256 + t], dv2));
            __syncthreads();
        }
        s[(size_t)atom * 128 + t] += ds;
        const size_t vb = (size_t)atom * 384;
        vnew[vb + t]       = vold[vb + t]       + dv0;
        vnew[vb + 128 + t] = vold[vb + 128 + t] + dv1;
        vnew[vb + 256 + t] = vold[vb + 256 + t] + dv2;
    }
}

// v_norm + concat:  cat[n, :128] = s[n], cat[n, 128:] = ||v_v[n, f, :]||
__global__ void normcat_kernel(const float* __restrict__ s, const float* __restrict__ vv,
                               float* __restrict__ cat) {
    int n = blockIdx.x;
    int t = threadIdx.x;
    size_t b = (size_t)n * 384;
    float a = vv[b + t], c = vv[b + 128 + t], d = vv[b + 256 + t];
    cat[(size_t)n * 256 + t] = s[(size_t)n * 128 + t];
    cat[(size_t)n * 256 + 128 + t] = sqrtf(a * a + c * c + d * d + 1e-12f);
}

// gated update:  v += u_v * a_vv ;  s += sum_d(u_v*v_v)*a_sv + a_ss
__global__ void update_kernel(float* __restrict__ s, float* __restrict__ v,
                              const float* __restrict__ uv, const float* __restrict__ vv,
                              const float* __restrict__ split) {
    int n = blockIdx.x;
    int t = threadIdx.x;
    size_t b = (size_t)n * 384;
    float avv = split[b + t];
    float asv = split[b + 128 + t];
    float ass = split[b + 256 + t];
    float dot = 0.0f;
#pragma unroll
    for (int x = 0; x < 3; x++) {
        float u_ = uv[b + x * 128 + t];
        float w_ = vv[b + x * 128 + t];
        dot = fmaf(u_, w_, dot);
        v[b + x * 128 + t] += u_ * avv;
    }
    s[(size_t)n * 128 + t] += dot * asv + ass;
}

// final N=5 projection: one warp per atom
__global__ void out_kernel(const float* __restrict__ h, const float* __restrict__ Wf3,
                           const float* __restrict__ bf3, float* __restrict__ out) {
    int gid = blockIdx.x * blockDim.x + threadIdx.x;
    int warp = gid >> 5;
    int lane = gid & 31;
    if (warp >= N_ATOMS) return;
    const float* hr = h + (size_t)warp * 128;
    float x0 = hr[lane], x1 = hr[32 + lane], x2 = hr[64 + lane], x3 = hr[96 + lane];
#pragma unroll
    for (int o = 0; o < 5; o++) {
        float p = x0 * Wf3[lane * 5 + o] + x1 * Wf3[(32 + lane) * 5 + o] +
                  x2 * Wf3[(64 + lane) * 5 + o] + x3 * Wf3[(96 + lane) * 5 + o];
#pragma unroll
        for (int off = 16; off; off >>= 1) p += __shfl_down_sync(0xffffffffu, p, off);
        if (lane == 0) out[(size_t)warp * 5 + o] = p + bf3[o];
    }
}

// ---------------- launch ----------------
extern "C" void kernel_launch(void* const* d_in, const int* in_sizes, int n_in,
                              void* d_out, int out_size) {
    const float* xyz   = (const float*)d_in[0];
    const int*   z     = (const int*)  d_in[1];
    const int*   nbrs  = (const int*)  d_in[2];
    const float* embed = (const float*)d_in[3];
    const float* W1  = (const float*)d_in[4];
    const float* b1  = (const float*)d_in[5];
    const float* W2  = (const float*)d_in[6];
    const float* b2  = (const float*)d_in[7];
    const float* Wd  = (const float*)d_in[8];
    const float* bd  = (const float*)d_in[9];
    const float* U   = (const float*)d_in[10];
    const float* V   = (const float*)d_in[11];
    const float* Ws1 = (const float*)d_in[12];
    const float* bs1 = (const float*)d_in[13];
    const float* Ws2 = (const float*)d_in[14];
    const float* bs2 = (const float*)d_in[15];
    const float* Wr1 = (const float*)d_in[16];
    const float* br1 = (const float*)d_in[17];
    const float* Wr2 = (const float*)d_in[18];
    const float* br2 = (const float*)d_in[19];
    const float* Wf1 = (const float*)d_in[20];
    const float* bf1 = (const float*)d_in[21];
    const float* Wf2 = (const float*)d_in[22];
    const float* bf2 = (const float*)d_in[23];
    const float* Wf3 = (const float*)d_in[24];
    const float* bf3 = (const float*)d_in[25];
    float* out = (float*)d_out;

    float *s, *vA, *vB, *phi, *uv, *vv, *cat, *t1, *t2, *af, *erbf;
    float4* eu4;
    int *cnt, *cur, *rowptr, *ej;
    cudaGetSymbolAddress((void**)&s, g_s);
    cudaGetSymbolAddress((void**)&vA, g_vA);
    cudaGetSymbolAddress((void**)&vB, g_vB);
    cudaGetSymbolAddress((void**)&phi, g_phi);
    cudaGetSymbolAddress((void**)&uv, g_uv);
    cudaGetSymbolAddress((void**)&vv, g_vv);
    cudaGetSymbolAddress((void**)&cat, g_cat);
    cudaGetSymbolAddress((void**)&t1, g_t1);
    cudaGetSymbolAddress((void**)&t2, g_t2);
    cudaGetSymbolAddress((void**)&af, g_af);
    cudaGetSymbolAddress((void**)&cnt, g_cnt);
    cudaGetSymbolAddress((void**)&cur, g_cur);
    cudaGetSymbolAddress((void**)&rowptr, g_rowptr);
    cudaGetSymbolAddress((void**)&ej, g_ej);
    cudaGetSymbolAddress((void**)&eu4, g_eu4);
    cudaGetSymbolAddress((void**)&erbf, g_erbf);

    // ---- preprocessing (every call; deterministic work) ----
    zero_i_kernel<<<(N_ATOMS + 255) / 256, 256>>>(cnt, N_ATOMS);
    zero_f_kernel<<<4096, 256>>>(vA, N_ATOMS * 384);
    init_s_kernel<<<(N_ATOMS * 128 + 255) / 256, 256>>>(s, embed, z);
    count_kernel<<<(N_EDGES + 255) / 256, 256>>>(cnt, nbrs);
    scan_kernel<<<1, 1024>>>(cnt, rowptr, cur);
    fill_kernel<<<(N_EDGES + 255) / 256, 256>>>(nbrs, xyz, cur, ej, eu4, erbf);

    const int GY_A = (N_ATOMS + 63) / 64;      // 313
    const int GY_V = (N_ATOMS * 3 + 63) / 64;  // 938

    float* vold = vA;
    float* vnew = vB;
    for (int l = 0; l < N_CONV; l++) {
        // phi = silu(s@W1+b1) @ W2 + b2
        sgemm_kernel<64, 128, 16, 1, 2, true><<<dim3(1, GY_A), 256>>>(
            s, W1 + (size_t)l * 128 * 128, b1 + l * 128, t1, N_ATOMS, 128, 128);
        sgemm_kernel<64, 128, 16, 1, 2, false><<<dim3(3, GY_A), 256>>>(
            t1, W2 + (size_t)l * 128 * 384, b2 + l * 384, phi, N_ATOMS, 384, 128);
        // message passing (gather-side)
        aggregate_kernel<<<1036, 128>>>(phi, vold, vnew, s,
                                        Wd + (size_t)l * N_RBF * 384, bd + l * 384,
                                        rowptr, ej, eu4, erbf);
        // u_v = v @ U,  v_v = v @ V  (flattened over 3 spatial dims)
        sgemm_kernel<64, 128, 16, 1, 2, false><<<dim3(1, GY_V), 256>>>(
            vnew, U + (size_t)l * 128 * 128, nullptr, uv, N_ATOMS * 3, 128, 128);
        sgemm_kernel<64, 128, 16, 1, 2, false><<<dim3(1, GY_V), 256>>>(
            vnew, V + (size_t)l * 128 * 128, nullptr, vv, N_ATOMS * 3, 128, 128);
        normcat_kernel<<<N_ATOMS, 128>>>(s, vv, cat);
        // split = silu(cat@Ws1+bs1) @ Ws2 + bs2
        sgemm_kernel<64, 128, 16, 1, 2, true><<<dim3(1, GY_A), 256>>>(
            cat, Ws1 + (size_t)l * 256 * 128, bs1 + l * 128, t1, N_ATOMS, 128, 256);
        sgemm_kernel<64, 128, 16, 1, 2, false><<<dim3(3, GY_A), 256>>>(
            t1, Ws2 + (size_t)l * 128 * 384, bs2 + l * 384, phi, N_ATOMS, 384, 128);
        update_kernel<<<N_ATOMS, 128>>>(s, vnew, uv, vv, phi);
        // ping-pong v
        float* tmp = vold; vold = vnew; vnew = tmp;
    }

    // readout
    sgemm_kernel<64, 128, 16, 1, 2, true><<<dim3(1, GY_A), 256>>>(
        s, Wr1, br1, t1, N_ATOMS, 128, 128);
    sgemm_kernel<64, 64, 16, 1, 1, false><<<dim3(1, GY_A), 256>>>(
        t1, Wr2, br2, af, N_ATOMS, 64, 128);
    sgemm_kernel<64, 128, 16, 1, 2, true><<<dim3(1, GY_A), 256>>>(
        af, Wf1, bf1, t2, N_ATOMS, 128, 64);
    sgemm_kernel<64, 128, 16, 1, 2, true><<<dim3(1, GY_A), 256>>>(
        t2, Wf2, bf2, t1, N_ATOMS, 128, 128);
    out_kernel<<<(N_ATOMS * 32 + 255) / 256, 256>>>(t1, Wf3, bf3, out);
}

// round 11
// speedup vs baseline: 1.0100x; 1.0100x over previous
#include <cuda_runtime.h>
#include <cuda_bf16.h>
#include <math.h>
#include <stdint.h>

#define N_ATOMS 20000
#define N_EDGES 320000
#define FEAT 128
#define N_RBF 20
#define N_CONV 3
#define CUTOFF 5.0f
#define PI_F 3.14159265358979323846f

typedef unsigned long long ull;

// ---------------- scratch (round-1 layout) ----------------
__device__ float g_s   [N_ATOMS * 128];
__device__ float g_vA  [N_ATOMS * 384];
__device__ float g_vB  [N_ATOMS * 384];
__device__ float g_phi [N_ATOMS * 384];
__device__ float g_uv  [N_ATOMS * 384];
__device__ float g_vv  [N_ATOMS * 384];
__device__ float g_cat [N_ATOMS * 256];
__device__ float g_t1  [N_ATOMS * 128];
__device__ float g_t2  [N_ATOMS * 128];
__device__ float g_af  [N_ATOMS * 64];
__device__ int   g_cnt [N_ATOMS];
__device__ int   g_cur [N_ATOMS];
__device__ int   g_rowptr[N_ATOMS + 1];
__device__ int   g_ej  [N_EDGES];
__device__ float4 g_eu4[N_EDGES];
__device__ float g_erbf[N_EDGES * N_RBF];

__device__ __forceinline__ float silu_f(float x) {
    return x / (1.0f + __expf(-x));
}

// packed f32x2 helpers (Blackwell base-family PTX, sm_100+)
__device__ __forceinline__ ull pack2(float lo, float hi) {
    ull u;
    asm("mov.b64 %0, {%1, %2};" : "=l"(u) : "f"(lo), "f"(hi));
    return u;
}
__device__ __forceinline__ void unpack2(ull u, float& lo, float& hi) {
    asm("mov.b64 {%0, %1}, %2;" : "=f"(lo), "=f"(hi) : "l"(u));
}
#define FMA2(d, a, b) \
    asm("fma.rn.f32x2 %0, %1, %2, %0;" : "+l"(d) : "l"(a), "l"(b))

// ---------------- small utility kernels (round-1 verbatim) ----------------
__global__ void zero_f_kernel(float* p, int n) {
    for (int i = blockIdx.x * blockDim.x + threadIdx.x; i < n; i += gridDim.x * blockDim.x)
        p[i] = 0.0f;
}
__global__ void zero_i_kernel(int* p, int n) {
    int i = blockIdx.x * blockDim.x + threadIdx.x;
    if (i < n) p[i] = 0;
}

__global__ void init_s_kernel(float* __restrict__ s, const float* __restrict__ embed,
                              const int* __restrict__ z) {
    int gid = blockIdx.x * blockDim.x + threadIdx.x;
    if (gid >= N_ATOMS * 128) return;
    int n = gid >> 7;
    int f = gid & 127;
    s[gid] = embed[z[n] * 128 + f];
}

__global__ void count_kernel(int* __restrict__ cnt, const int* __restrict__ nbrs) {
    int e = blockIdx.x * blockDim.x + threadIdx.x;
    if (e >= N_EDGES) return;
    atomicAdd(&cnt[nbrs[2 * e]], 1);
}

__global__ void scan_kernel(const int* __restrict__ cnt, int* __restrict__ rowptr,
                            int* __restrict__ cur) {
    __shared__ int part[1024];
    const int t = threadIdx.x;
    const int CH = (N_ATOMS + 1023) / 1024;  // 20
    int base = t * CH;
    int sum = 0;
    for (int i = 0; i < CH; i++) {
        int a = base + i;
        if (a < N_ATOMS) sum += cnt[a];
    }
    part[t] = sum;
    __syncthreads();
    for (int d = 1; d < 1024; d <<= 1) {
        int add = (t >= d) ? part[t - d] : 0;
        __syncthreads();
        part[t] += add;
        __syncthreads();
    }
    int run = part[t] - sum;  // exclusive prefix
    for (int i = 0; i < CH; i++) {
        int a = base + i;
        if (a < N_ATOMS) {
            rowptr[a] = run;
            cur[a] = run;
            run += cnt[a];
        }
    }
    if (t == 1023) rowptr[N_ATOMS] = part[1023];
}

__global__ void fill_kernel(const int* __restrict__ nbrs, const float* __restrict__ xyz,
                            int* __restrict__ cur, int* __restrict__ ej,
                            float4* __restrict__ eu4, float* __restrict__ erbf) {
    int e = blockIdx.x * blockDim.x + threadIdx.x;
    if (e >= N_EDGES) return;
    int i = nbrs[2 * e];
    int j = nbrs[2 * e + 1];
    float rx = xyz[3 * j + 0] - xyz[3 * i + 0];
    float ry = xyz[3 * j + 1] - xyz[3 * i + 1];
    float rz = xyz[3 * j + 2] - xyz[3 * i + 2];
    float d2 = rx * rx + ry * ry + rz * rz + 1e-12f;
    float d = sqrtf(d2);
    float inv = 1.0f / d;
    float fc = (d < CUTOFF) ? 0.5f * (cosf(PI_F * d / CUTOFF) + 1.0f) : 0.0f;
    int pos = atomicAdd(&cur[i], 1);
    ej[pos] = j;
    eu4[pos] = make_float4(rx * inv, ry * inv, rz * inv, fc);
    float invfc = inv * fc;
    float arg = PI_F * d / CUTOFF;
#pragma unroll
    for (int k = 0; k < N_RBF; k++) {
        erbf[(size_t)pos * N_RBF + k] = sinf((float)(k + 1) * arg) * invfc;
    }
}

// ================= packed-f32x2 SGEMM =================
// C[M,N] = act( A[M,K] @ B[K,N] + bias );  B is the raw weight [K,N] row-major.
// 128x128 CTA tile, BK=16, 256 threads, 8x8 per-thread accumulators held packed.
#define BK 16
#define LDA 132
#define LDB 132

template <bool ACT>
__global__ __launch_bounds__(256)
void sgemm2(const float* __restrict__ A, const float* __restrict__ B,
            const float* __restrict__ bias, float* __restrict__ C,
            int M, int N, int K) {
    __shared__ float As[BK][LDA];
    __shared__ float Bs[BK][LDB];
    const int tid = threadIdx.x;
    const int tx = tid & 15;    // N dir, 8 cols each
    const int ty = tid >> 4;    // M dir, 8 rows each
    const int m0 = blockIdx.y * 128;
    const int n0 = blockIdx.x * 128;
    const int my0 = ty * 8;
    const int nx0 = tx * 8;

    ull acc[8][4];
#pragma unroll
    for (int i = 0; i < 8; i++)
#pragma unroll
        for (int j = 0; j < 4; j++) acc[i][j] = pack2(0.0f, 0.0f);

    for (int k0 = 0; k0 < K; k0 += BK) {
        // stage A (transposed) : As[kk][m] = A[(m0+m)*K + k0+kk]
#pragma unroll
        for (int q = tid; q < 512; q += 256) {
            int m = q >> 2;
            int k4 = (q & 3) << 2;
            float4 v = make_float4(0.f, 0.f, 0.f, 0.f);
            int gm = m0 + m;
            if (gm < M) v = *(const float4*)&A[(size_t)gm * K + k0 + k4];
            As[k4 + 0][m] = v.x;
            As[k4 + 1][m] = v.y;
            As[k4 + 2][m] = v.z;
            As[k4 + 3][m] = v.w;
        }
        // stage B : Bs[kk][n] = B[(k0+kk)*N + n0+n]
#pragma unroll
        for (int q = tid; q < 512; q += 256) {
            int kk = q >> 5;
            int n4 = (q & 31) << 2;
            float4 v = make_float4(0.f, 0.f, 0.f, 0.f);
            if (n0 + n4 < N) v = *(const float4*)&B[(size_t)(k0 + kk) * N + n0 + n4];
            *(float4*)&Bs[kk][n4] = v;
        }
        __syncthreads();

#pragma unroll
        for (int kk = 0; kk < BK; kk++) {
            float4 a0 = *(const float4*)&As[kk][my0];
            float4 a1 = *(const float4*)&As[kk][my0 + 4];
            float4 b0 = *(const float4*)&Bs[kk][nx0];
            float4 b1 = *(const float4*)&Bs[kk][nx0 + 4];
            ull bv[4];
            bv[0] = pack2(b0.x, b0.y);
            bv[1] = pack2(b0.z, b0.w);
            bv[2] = pack2(b1.x, b1.y);
            bv[3] = pack2(b1.z, b1.w);
            float ar[8] = {a0.x, a0.y, a0.z, a0.w, a1.x, a1.y, a1.z, a1.w};
#pragma unroll
            for (int i = 0; i < 8; i++) {
                ull av = pack2(ar[i], ar[i]);
#pragma unroll
                for (int j = 0; j < 4; j++) FMA2(acc[i][j], av, bv[j]);
            }
        }
        __syncthreads();
    }

    // epilogue
#pragma unroll
    for (int i = 0; i < 8; i++) {
        int gm = m0 + my0 + i;
        if (gm >= M) continue;
#pragma unroll
        for (int j = 0; j < 4; j++) {
            int gn = n0 + nx0 + j * 2;
            if (gn >= N) continue;
            float f0, f1;
            unpack2(acc[i][j], f0, f1);
            if (bias) { f0 += bias[gn]; f1 += bias[gn + 1]; }
            if (ACT) { f0 = silu_f(f0); f1 = silu_f(f1); }
            *(float2*)&C[(size_t)gm * N + gn] = make_float2(f0, f1);
        }
    }
}

// ---------------- edge aggregation (round-1 verbatim: per-edge, no batching) ----------------
__global__ void aggregate_kernel(const float* __restrict__ phi, const float* __restrict__ vold,
                                 float* __restrict__ vnew, float* __restrict__ s,
                                 const float* __restrict__ Wd, const float* __restrict__ bd,
                                 const int* __restrict__ rowptr, const int* __restrict__ ej,
                                 const float4* __restrict__ eu4, const float* __restrict__ erbf) {
    __shared__ float sWd[N_RBF * 384];
    __shared__ float sRbf[N_RBF];
    const int t = threadIdx.x;  // 128 threads = one feature each
    for (int idx = t; idx < N_RBF * 384; idx += 128) sWd[idx] = Wd[idx];
    const float bd0 = bd[t];
    const float bd1 = bd[128 + t];
    const float bd2 = bd[256 + t];
    __syncthreads();

    for (int atom = blockIdx.x; atom < N_ATOMS; atom += gridDim.x) {
        const int e0 = rowptr[atom];
        const int e1 = rowptr[atom + 1];
        float ds = 0.0f, dv0 = 0.0f, dv1 = 0.0f, dv2 = 0.0f;
        for (int e = e0; e < e1; e++) {
            const int j = ej[e];
            const float4 u = eu4[e];
            if (t < N_RBF) sRbf[t] = erbf[(size_t)e * N_RBF + t];
            __syncthreads();
            float ws0 = bd0 * u.w, ws1 = bd1 * u.w, ws2 = bd2 * u.w;
#pragma unroll
            for (int k = 0; k < N_RBF; k++) {
                float r = sRbf[k];
                ws0 = fmaf(r, sWd[k * 384 + t], ws0);
                ws1 = fmaf(r, sWd[k * 384 + 128 + t], ws1);
                ws2 = fmaf(r, sWd[k * 384 + 256 + t], ws2);
            }
            const float* pj = phi + (size_t)j * 384;
            const float inv0 = pj[t] * ws0;
            const float inv1 = pj[128 + t] * ws1;
            const float inv2 = pj[256 + t] * ws2;
            ds += inv1;
            const float* vj = vold + (size_t)j * 384;
            dv0 = fmaf(u.x, inv2, fmaf(inv0, vj[t], dv0));
            dv1 = fmaf(u.y, inv2, fmaf(inv0, vj[128 + t], dv1));
            dv2 = fmaf(u.z, inv2, fmaf(inv0, vj[256 + t], dv2));
            __syncthreads();
        }
        s[(size_t)atom * 128 + t] += ds;
        const size_t vb = (size_t)atom * 384;
        vnew[vb + t]       = vold[vb + t]       + dv0;
        vnew[vb + 128 + t] = vold[vb + 128 + t] + dv1;
        vnew[vb + 256 + t] = vold[vb + 256 + t] + dv2;
    }
}

// v_norm + concat:  cat[n, :128] = s[n], cat[n, 128:] = ||v_v[n, f, :]||
__global__ void normcat_kernel(const float* __restrict__ s, const float* __restrict__ vv,
                               float* __restrict__ cat) {
    int n = blockIdx.x;
    int t = threadIdx.x;
    size_t b = (size_t)n * 384;
    float a = vv[b + t], c = vv[b + 128 + t], d = vv[b + 256 + t];
    cat[(size_t)n * 256 + t] = s[(size_t)n * 128 + t];
    cat[(size_t)n * 256 + 128 + t] = sqrtf(a * a + c * c + d * d + 1e-12f);
}

// gated update:  v += u_v * a_vv ;  s += sum_d(u_v*v_v)*a_sv + a_ss
__global__ void update_kernel(float* __restrict__ s, float* __restrict__ v,
                              const float* __restrict__ uv, const float* __restrict__ vv,
                              const float* __restrict__ split) {
    int n = blockIdx.x;
    int t = threadIdx.x;
    size_t b = (size_t)n * 384;
    float avv = split[b + t];
    float asv = split[b + 128 + t];
    float ass = split[b + 256 + t];
    float dot = 0.0f;
#pragma unroll
    for (int x = 0; x < 3; x++) {
        float u_ = uv[b + x * 128 + t];
        float w_ = vv[b + x * 128 + t];
        dot = fmaf(u_, w_, dot);
        v[b + x * 128 + t] += u_ * avv;
    }
    s[(size_t)n * 128 + t] += dot * asv + ass;
}

// final N=5 projection: one warp per atom
__global__ void out_kernel(const float* __restrict__ h, const float* __restrict__ Wf3,
                           const float* __restrict__ bf3, float* __restrict__ out) {
    int gid = blockIdx.x * blockDim.x + threadIdx.x;
    int warp = gid >> 5;
    int lane = gid & 31;
    if (warp >= N_ATOMS) return;
    const float* hr = h + (size_t)warp * 128;
    float x0 = hr[lane], x1 = hr[32 + lane], x2 = hr[64 + lane], x3 = hr[96 + lane];
#pragma unroll
    for (int o = 0; o < 5; o++) {
        float p = x0 * Wf3[lane * 5 + o] + x1 * Wf3[(32 + lane) * 5 + o] +
                  x2 * Wf3[(64 + lane) * 5 + o] + x3 * Wf3[(96 + lane) * 5 + o];
#pragma unroll
        for (int off = 16; off; off >>= 1) p += __shfl_down_sync(0xffffffffu, p, off);
        if (lane == 0) out[(size_t)warp * 5 + o] = p + bf3[o];
    }
}

// ---------------- launch ----------------
extern "C" void kernel_launch(void* const* d_in, const int* in_sizes, int n_in,
                              void* d_out, int out_size) {
    const float* xyz   = (const float*)d_in[0];
    const int*   z     = (const int*)  d_in[1];
    const int*   nbrs  = (const int*)  d_in[2];
    const float* embed = (const float*)d_in[3];
    const float* W1  = (const float*)d_in[4];
    const float* b1  = (const float*)d_in[5];
    const float* W2  = (const float*)d_in[6];
    const float* b2  = (const float*)d_in[7];
    const float* Wd  = (const float*)d_in[8];
    const float* bd  = (const float*)d_in[9];
    const float* U   = (const float*)d_in[10];
    const float* V   = (const float*)d_in[11];
    const float* Ws1 = (const float*)d_in[12];
    const float* bs1 = (const float*)d_in[13];
    const float* Ws2 = (const float*)d_in[14];
    const float* bs2 = (const float*)d_in[15];
    const float* Wr1 = (const float*)d_in[16];
    const float* br1 = (const float*)d_in[17];
    const float* Wr2 = (const float*)d_in[18];
    const float* br2 = (const float*)d_in[19];
    const float* Wf1 = (const float*)d_in[20];
    const float* bf1 = (const float*)d_in[21];
    const float* Wf2 = (const float*)d_in[22];
    const float* bf2 = (const float*)d_in[23];
    const float* Wf3 = (const float*)d_in[24];
    const float* bf3 = (const float*)d_in[25];
    float* out = (float*)d_out;

    float *s, *vA, *vB, *phi, *uv, *vv, *cat, *t1, *t2, *af, *erbf;
    float4* eu4;
    int *cnt, *cur, *rowptr, *ej;
    cudaGetSymbolAddress((void**)&s, g_s);
    cudaGetSymbolAddress((void**)&vA, g_vA);
    cudaGetSymbolAddress((void**)&vB, g_vB);
    cudaGetSymbolAddress((void**)&phi, g_phi);
    cudaGetSymbolAddress((void**)&uv, g_uv);
    cudaGetSymbolAddress((void**)&vv, g_vv);
    cudaGetSymbolAddress((void**)&cat, g_cat);
    cudaGetSymbolAddress((void**)&t1, g_t1);
    cudaGetSymbolAddress((void**)&t2, g_t2);
    cudaGetSymbolAddress((void**)&af, g_af);
    cudaGetSymbolAddress((void**)&cnt, g_cnt);
    cudaGetSymbolAddress((void**)&cur, g_cur);
    cudaGetSymbolAddress((void**)&rowptr, g_rowptr);
    cudaGetSymbolAddress((void**)&ej, g_ej);
    cudaGetSymbolAddress((void**)&eu4, g_eu4);
    cudaGetSymbolAddress((void**)&erbf, g_erbf);

    // ---- preprocessing (round-1 verbatim) ----
    zero_i_kernel<<<(N_ATOMS + 255) / 256, 256>>>(cnt, N_ATOMS);
    zero_f_kernel<<<4096, 256>>>(vA, N_ATOMS * 384);
    init_s_kernel<<<(N_ATOMS * 128 + 255) / 256, 256>>>(s, embed, z);
    count_kernel<<<(N_EDGES + 255) / 256, 256>>>(cnt, nbrs);
    scan_kernel<<<1, 1024>>>(cnt, rowptr, cur);
    fill_kernel<<<(N_EDGES + 255) / 256, 256>>>(nbrs, xyz, cur, ej, eu4, erbf);

    const int GA = (N_ATOMS + 127) / 128;      // 157
    const int GV = (N_ATOMS * 3 + 127) / 128;  // 469

    float* vold = vA;
    float* vnew = vB;
    for (int l = 0; l < N_CONV; l++) {
        // t1 = silu(s@W1+b1)
        sgemm2<true><<<dim3(1, GA), 256>>>(
            s, W1 + (size_t)l * 128 * 128, b1 + l * 128, t1, N_ATOMS, 128, 128);
        // phi = t1@W2+b2
        sgemm2<false><<<dim3(3, GA), 256>>>(
            t1, W2 + (size_t)l * 128 * 384, b2 + l * 384, phi, N_ATOMS, 384, 128);
        // message passing (round-1 per-edge aggregation)
        aggregate_kernel<<<1036, 128>>>(phi, vold, vnew, s,
                                        Wd + (size_t)l * N_RBF * 384, bd + l * 384,
                                        rowptr, ej, eu4, erbf);
        // u_v = v @ U,  v_v = v @ V  (flattened over 3 spatial dims)
        sgemm2<false><<<dim3(1, GV), 256>>>(
            vnew, U + (size_t)l * 128 * 128, nullptr, uv, N_ATOMS * 3, 128, 128);
        sgemm2<false><<<dim3(1, GV), 256>>>(
            vnew, V + (size_t)l * 128 * 128, nullptr, vv, N_ATOMS * 3, 128, 128);
        normcat_kernel<<<N_ATOMS, 128>>>(s, vv, cat);
        // split = silu(cat@Ws1+bs1) @ Ws2 + bs2
        sgemm2<true><<<dim3(1, GA), 256>>>(
            cat, Ws1 + (size_t)l * 256 * 128, bs1 + l * 128, t1, N_ATOMS, 128, 256);
        sgemm2<false><<<dim3(3, GA), 256>>>(
            t1, Ws2 + (size_t)l * 128 * 384, bs2 + l * 384, phi, N_ATOMS, 384, 128);
        update_kernel<<<N_ATOMS, 128>>>(s, vnew, uv, vv, phi);
        // ping-pong v
        float* tmp = vold; vold = vnew; vnew = tmp;
    }

    // readout
    sgemm2<true><<<dim3(1, GA), 256>>>(s, Wr1, br1, t1, N_ATOMS, 128, 128);
    sgemm2<false><<<dim3(1, GA), 256>>>(t1, Wr2, br2, af, N_ATOMS, 64, 128);
    sgemm2<true><<<dim3(1, GA), 256>>>(af, Wf1, bf1, t2, N_ATOMS, 128, 64);
    sgemm2<true><<<dim3(1, GA), 256>>>(t2, Wf2, bf2, t1, N_ATOMS, 128, 128);
    out_kernel<<<(N_ATOMS * 32 + 255) / 256, 256>>>(t1, Wf3, bf3, out);
}